// round 4
// baseline (speedup 1.0000x reference)
#include <cuda_runtime.h>
#include <cuda_bf16.h>

// Varifold loss on GB300 — factored Gaussian + f32x2 packed math + triangular tiles.
// loss = (1/B) * sum_b [ K(s,s) + K(t,t) - 2 K(s,t) ]
// K(X,Y) = sum_ij Lx_i Ly_j exp(-gamma |Cx_i - Cy_j|^2) <Nx_i, Ny_j>^2
//
// Factorization:
//   M' = sqrt(L) * Nn * exp(-|c'|^2 / 2)   with c' = C / sigma
//   cs = c' * sqrt(2*log2(e))
//   term_ij = <M'_i, M'_j>^2 * 2^( <cs_i, cs_j> )

#define NV_CONST 5023
#define TI 1024          // i-points per block (128 threads x 8)
#define TJ 512           // j-points per smem tile
#define BLOCK 128
#define NG 4             // 4 f32x2 groups = 8 i-points per thread
#define NFP_MAX 10240
#define SMAX 8
#define PART_MAX 8192

__device__ float4 g_A[SMAX * NFP_MAX];   // (cs.x, cs.y, cs.z, M'.x)
__device__ float4 g_Bv[SMAX * NFP_MAX];  // (M'.y, M'.z, 0, 0)
__device__ double g_part[PART_MAX];

typedef unsigned long long ull;

__device__ __forceinline__ ull pk(float a, float b) {
    ull r; asm("mov.b64 %0, {%1,%2};" : "=l"(r) : "f"(a), "f"(b)); return r;
}
__device__ __forceinline__ void upk(ull v, float& a, float& b) {
    asm("mov.b64 {%0,%1}, %2;" : "=f"(a), "=f"(b) : "l"(v));
}
__device__ __forceinline__ ull f2mul(ull a, ull b) {
    ull r; asm("mul.rn.f32x2 %0, %1, %2;" : "=l"(r) : "l"(a), "l"(b)); return r;
}
__device__ __forceinline__ ull f2fma(ull a, ull b, ull c) {
    ull r; asm("fma.rn.f32x2 %0, %1, %2, %3;" : "=l"(r) : "l"(a), "l"(b), "l"(c)); return r;
}
__device__ __forceinline__ float ex2(float x) {
    float r; asm("ex2.approx.f32 %0, %1;" : "=f"(r) : "f"(x)); return r;
}

__global__ void prep_kernel(const float* __restrict__ pred,
                            const float* __restrict__ targ,
                            const int* __restrict__ faces,
                            int B, int NV, int NF, int NFP)
{
    int idx = blockIdx.x * blockDim.x + threadIdx.x;
    int total = 2 * B * NFP;
    if (idx >= total) return;
    int s = idx / NFP;
    int f = idx - s * NFP;

    float4 A = make_float4(0.f, 0.f, 0.f, 0.f);
    float4 Bv = make_float4(0.f, 0.f, 0.f, 0.f);

    if (f < NF) {
        const float* src = (s < B) ? pred : targ;
        int b = (s < B) ? s : (s - B);
        const float* base = src + (size_t)b * NV * 3;

        int i0 = faces[3 * f + 0];
        int i1 = faces[3 * f + 1];
        int i2 = faces[3 * f + 2];

        float x0 = base[3 * i0 + 0], y0 = base[3 * i0 + 1], z0 = base[3 * i0 + 2];
        float x1 = base[3 * i1 + 0], y1 = base[3 * i1 + 1], z1 = base[3 * i1 + 2];
        float x2 = base[3 * i2 + 0], y2 = base[3 * i2 + 1], z2 = base[3 * i2 + 2];

        // c' = centroid / sigma  (sigma = 0.03)
        const float SG = 33.333333333333336f;
        float cx = (x0 + x1 + x2) * (1.0f / 3.0f) * SG;
        float cy = (y0 + y1 + y2) * (1.0f / 3.0f) * SG;
        float cz = (z0 + z1 + z2) * (1.0f / 3.0f) * SG;

        float e1x = x1 - x0, e1y = y1 - y0, e1z = z1 - z0;
        float e2x = x2 - x0, e2y = y2 - y0, e2z = z2 - z0;

        float nx = 0.5f * (e1y * e2z - e1z * e2y);
        float ny = 0.5f * (e1z * e2x - e1x * e2z);
        float nz = 0.5f * (e1x * e2y - e1y * e2x);

        float L = sqrtf(nx * nx + ny * ny + nz * nz);
        // M' = sqrt(L)/max(L,eps) * N * exp(-|c'|^2/2)
        float w = expf(-0.5f * (cx * cx + cy * cy + cz * cz));
        float sc = (sqrtf(L) / fmaxf(L, 1e-12f)) * w;
        float mx = nx * sc, my = ny * sc, mz = nz * sc;

        // cs = c' * sqrt(2*log2(e))  so that dot(cs_i,cs_j) feeds EX2 directly
        const float SQ2LE = 1.6986436006287996f;  // sqrt(2*1.4426950408889634)
        A = make_float4(cx * SQ2LE, cy * SQ2LE, cz * SQ2LE, mx);
        Bv = make_float4(my, mz, 0.f, 0.f);
    }
    g_A[(size_t)s * NFP + f] = A;
    g_Bv[(size_t)s * NFP + f] = Bv;
}

__global__ void __launch_bounds__(BLOCK)
pair_kernel(int B, int NFP, int gx, int gy)
{
    // j-tile stored pre-duplicated: each field is a packed {v,v} 64-bit value,
    // so the inner loop reads broadcast ld.shared.b64 with zero packing MOVs.
    __shared__ ull s_jx[TJ], s_jy[TJ], s_jz[TJ];
    __shared__ ull s_mx[TJ], s_my[TJ], s_mz[TJ];
    __shared__ float red[BLOCK];

    int z = blockIdx.z;
    int b = z / 3;
    int t = z - 3 * b;           // 0: ss, 1: tt, 2: st
    int pidx = (z * gy + blockIdx.y) * gx + blockIdx.x;

    float wgt = (t == 2) ? -2.f : 1.f;
    if (t < 2) {
        // symmetric kernel: i-block x (1024 rows) spans j-tiles [2x, 2x+2)
        int jt = blockIdx.y, lo = blockIdx.x * 2;
        if (jt < lo) {                    // strictly lower triangle: skip
            if (threadIdx.x == 0) g_part[pidx] = 0.0;
            return;
        }
        if (jt >= lo + 2) wgt = 2.f;      // strictly upper: count twice
    }

    int sx = (t == 1) ? (B + b) : b;
    int sy = (t == 0) ? b : (B + b);

    const float4* __restrict__ XA = g_A  + (size_t)sx * NFP;
    const float4* __restrict__ XB = g_Bv + (size_t)sx * NFP;
    const float4* __restrict__ YA = g_A  + (size_t)sy * NFP;
    const float4* __restrict__ YB = g_Bv + (size_t)sy * NFP;

    // Load 8 i-points, packed as 4 f32x2 groups
    int i0 = blockIdx.x * TI + threadIdx.x;
    ull icx[NG], icy[NG], icz[NG], imx[NG], imy[NG], imz[NG];
#pragma unroll
    for (int g = 0; g < NG; g++) {
        float4 a0 = XA[i0 + (2 * g) * BLOCK];
        float4 a1 = XA[i0 + (2 * g + 1) * BLOCK];
        float4 b0 = XB[i0 + (2 * g) * BLOCK];
        float4 b1 = XB[i0 + (2 * g + 1) * BLOCK];
        icx[g] = pk(a0.x, a1.x);
        icy[g] = pk(a0.y, a1.y);
        icz[g] = pk(a0.z, a1.z);
        imx[g] = pk(a0.w, a1.w);
        imy[g] = pk(b0.x, b1.x);
        imz[g] = pk(b0.y, b1.y);
    }

    int j0 = blockIdx.y * TJ;
#pragma unroll
    for (int r = 0; r < TJ / BLOCK; r++) {
        int jj = threadIdx.x + r * BLOCK;
        float4 a = YA[j0 + jj];
        float4 bb = YB[j0 + jj];
        s_jx[jj] = pk(a.x, a.x);
        s_jy[jj] = pk(a.y, a.y);
        s_jz[jj] = pk(a.z, a.z);
        s_mx[jj] = pk(a.w, a.w);
        s_my[jj] = pk(bb.x, bb.x);
        s_mz[jj] = pk(bb.y, bb.y);
    }
    __syncthreads();

    ull acc[NG];
#pragma unroll
    for (int g = 0; g < NG; g++) acc[g] = 0ull;   // (0.0f, 0.0f)

#pragma unroll 2
    for (int j = 0; j < TJ; j++) {
        ull jx  = s_jx[j];
        ull jy  = s_jy[j];
        ull jz  = s_jz[j];
        ull jmx = s_mx[j];
        ull jmy = s_my[j];
        ull jmz = s_mz[j];
#pragma unroll
        for (int g = 0; g < NG; g++) {
            ull pc = f2fma(jz, icz[g], f2fma(jy, icy[g], f2mul(jx, icx[g])));
            ull dm = f2fma(jmz, imz[g], f2fma(jmy, imy[g], f2mul(jmx, imx[g])));
            float p0, p1; upk(pc, p0, p1);
            float e0 = ex2(p0);
            float e1 = ex2(p1);
            ull dm2 = f2mul(dm, dm);
            acc[g] = f2fma(dm2, pk(e0, e1), acc[g]);
        }
    }

    float tsum = 0.f;
#pragma unroll
    for (int g = 0; g < NG; g++) {
        float a0, a1; upk(acc[g], a0, a1);
        tsum += a0 + a1;
    }
    red[threadIdx.x] = tsum;
    __syncthreads();
#pragma unroll
    for (int s2 = BLOCK / 2; s2 > 0; s2 >>= 1) {
        if (threadIdx.x < s2) red[threadIdx.x] += red[threadIdx.x + s2];
        __syncthreads();
    }
    if (threadIdx.x == 0) {
        g_part[pidx] = (double)wgt * (double)red[0];
    }
}

__global__ void reduce_kernel(float* __restrict__ out, int n, float invB)
{
    __shared__ double rd[256];
    double s = 0.0;
    for (int i = threadIdx.x; i < n; i += 256) s += g_part[i];
    rd[threadIdx.x] = s;
    __syncthreads();
#pragma unroll
    for (int s2 = 128; s2 > 0; s2 >>= 1) {
        if (threadIdx.x < s2) rd[threadIdx.x] += rd[threadIdx.x + s2];
        __syncthreads();
    }
    if (threadIdx.x == 0) out[0] = (float)(rd[0] * (double)invB);
}

extern "C" void kernel_launch(void* const* d_in, const int* in_sizes, int n_in,
                              void* d_out, int out_size)
{
    const float* pred  = (const float*)d_in[0];
    const float* targ  = (const float*)d_in[1];
    const int*   faces = (const int*)d_in[2];

    int NV = NV_CONST;
    int B  = in_sizes[0] / (NV * 3);
    int NF = in_sizes[2] / 3;
    int NFP = ((NF + TI - 1) / TI) * TI;   // multiple of 1024 (and of TJ=512)
    if (NFP > NFP_MAX) NFP = NFP_MAX;
    if (B > SMAX / 2) B = SMAX / 2;

    int prep_total = 2 * B * NFP;
    prep_kernel<<<(prep_total + 255) / 256, 256>>>(pred, targ, faces, B, NV, NF, NFP);

    int gx = NFP / TI;
    int gy = NFP / TJ;
    dim3 grid(gx, gy, 3 * B);
    pair_kernel<<<grid, BLOCK>>>(B, NFP, gx, gy);

    int nparts = gx * gy * 3 * B;
    reduce_kernel<<<1, 256>>>((float*)d_out, nparts, 1.0f / (float)B);
}

// round 5
// speedup vs baseline: 1.1390x; 1.1390x over previous
#include <cuda_runtime.h>
#include <cuda_bf16.h>

// Varifold loss on GB300 — factored Gaussian + f32x2 packed math + triangular tiles.
// loss = (1/B) * sum_b [ K(s,s) + K(t,t) - 2 K(s,t) ]
// K(X,Y) = sum_ij Lx_i Ly_j exp(-gamma |Cx_i - Cy_j|^2) <Nx_i, Ny_j>^2
//
// Factorization:
//   M' = sqrt(L) * Nn * exp(-|c'|^2 / 2)   with c' = C / sigma
//   cs = c' * sqrt(2*log2(e))
//   term_ij = <M'_i, M'_j>^2 * 2^( <cs_i, cs_j> )

#define NV_CONST 5023
#define TI 2048          // i-points per block (256 threads x 8)
#define TJ 512           // j-points per smem tile
#define BLOCK 256
#define NG 4             // 4 f32x2 groups = 8 i-points per thread
#define NFP_MAX 10240
#define SMAX 8
#define PART_MAX 8192

__device__ float4 g_A[SMAX * NFP_MAX];   // (cs.x, cs.y, cs.z, M'.x)
__device__ float4 g_Bv[SMAX * NFP_MAX];  // (M'.y, M'.z, 0, 0)
__device__ double g_part[PART_MAX];

typedef unsigned long long ull;

__device__ __forceinline__ ull pk(float a, float b) {
    ull r; asm("mov.b64 %0, {%1,%2};" : "=l"(r) : "f"(a), "f"(b)); return r;
}
__device__ __forceinline__ void upk(ull v, float& a, float& b) {
    asm("mov.b64 {%0,%1}, %2;" : "=f"(a), "=f"(b) : "l"(v));
}
__device__ __forceinline__ ull f2mul(ull a, ull b) {
    ull r; asm("mul.rn.f32x2 %0, %1, %2;" : "=l"(r) : "l"(a), "l"(b)); return r;
}
__device__ __forceinline__ ull f2fma(ull a, ull b, ull c) {
    ull r; asm("fma.rn.f32x2 %0, %1, %2, %3;" : "=l"(r) : "l"(a), "l"(b), "l"(c)); return r;
}
__device__ __forceinline__ float ex2(float x) {
    float r; asm("ex2.approx.f32 %0, %1;" : "=f"(r) : "f"(x)); return r;
}

__global__ void prep_kernel(const float* __restrict__ pred,
                            const float* __restrict__ targ,
                            const int* __restrict__ faces,
                            int B, int NV, int NF, int NFP)
{
    int idx = blockIdx.x * blockDim.x + threadIdx.x;
    int total = 2 * B * NFP;
    if (idx >= total) return;
    int s = idx / NFP;
    int f = idx - s * NFP;

    float4 A = make_float4(0.f, 0.f, 0.f, 0.f);
    float4 Bv = make_float4(0.f, 0.f, 0.f, 0.f);

    if (f < NF) {
        const float* src = (s < B) ? pred : targ;
        int b = (s < B) ? s : (s - B);
        const float* base = src + (size_t)b * NV * 3;

        int i0 = faces[3 * f + 0];
        int i1 = faces[3 * f + 1];
        int i2 = faces[3 * f + 2];

        float x0 = base[3 * i0 + 0], y0 = base[3 * i0 + 1], z0 = base[3 * i0 + 2];
        float x1 = base[3 * i1 + 0], y1 = base[3 * i1 + 1], z1 = base[3 * i1 + 2];
        float x2 = base[3 * i2 + 0], y2 = base[3 * i2 + 1], z2 = base[3 * i2 + 2];

        // c' = centroid / sigma  (sigma = 0.03)
        const float SG = 33.333333333333336f;
        float cx = (x0 + x1 + x2) * (1.0f / 3.0f) * SG;
        float cy = (y0 + y1 + y2) * (1.0f / 3.0f) * SG;
        float cz = (z0 + z1 + z2) * (1.0f / 3.0f) * SG;

        float e1x = x1 - x0, e1y = y1 - y0, e1z = z1 - z0;
        float e2x = x2 - x0, e2y = y2 - y0, e2z = z2 - z0;

        float nx = 0.5f * (e1y * e2z - e1z * e2y);
        float ny = 0.5f * (e1z * e2x - e1x * e2z);
        float nz = 0.5f * (e1x * e2y - e1y * e2x);

        float L = sqrtf(nx * nx + ny * ny + nz * nz);
        // M' = sqrt(L)/max(L,eps) * N * exp(-|c'|^2/2)
        float w = expf(-0.5f * (cx * cx + cy * cy + cz * cz));
        float sc = (sqrtf(L) / fmaxf(L, 1e-12f)) * w;
        float mx = nx * sc, my = ny * sc, mz = nz * sc;

        // cs = c' * sqrt(2*log2(e))  so that dot(cs_i,cs_j) feeds EX2 directly
        const float SQ2LE = 1.6986436006287996f;  // sqrt(2*1.4426950408889634)
        A = make_float4(cx * SQ2LE, cy * SQ2LE, cz * SQ2LE, mx);
        Bv = make_float4(my, mz, 0.f, 0.f);
    }
    g_A[(size_t)s * NFP + f] = A;
    g_Bv[(size_t)s * NFP + f] = Bv;
}

__global__ void __launch_bounds__(BLOCK, 3)
pair_kernel(int B, int NFP, int gx, int gy)
{
    __shared__ float4 sA[TJ];
    __shared__ float4 sB[TJ];
    __shared__ float red[BLOCK];

    int z = blockIdx.z;
    int b = z / 3;
    int t = z - 3 * b;           // 0: ss, 1: tt, 2: st
    int pidx = (z * gy + blockIdx.y) * gx + blockIdx.x;

    float wgt = (t == 2) ? -2.f : 1.f;
    if (t < 2) {
        // symmetric kernel: i-block x (2048 rows) spans j-tiles [4x, 4x+4)
        int jt = blockIdx.y, lo = blockIdx.x * 4;
        if (jt < lo) {                    // strictly lower triangle: skip
            if (threadIdx.x == 0) g_part[pidx] = 0.0;
            return;
        }
        if (jt >= lo + 4) wgt = 2.f;      // strictly upper: count twice
    }

    int sx = (t == 1) ? (B + b) : b;
    int sy = (t == 0) ? b : (B + b);

    const float4* __restrict__ XA = g_A  + (size_t)sx * NFP;
    const float4* __restrict__ XB = g_Bv + (size_t)sx * NFP;
    const float4* __restrict__ YA = g_A  + (size_t)sy * NFP;
    const float4* __restrict__ YB = g_Bv + (size_t)sy * NFP;

    // Load 8 i-points, packed as 4 f32x2 groups
    int i0 = blockIdx.x * TI + threadIdx.x;
    ull icx[NG], icy[NG], icz[NG], imx[NG], imy[NG], imz[NG];
#pragma unroll
    for (int g = 0; g < NG; g++) {
        float4 a0 = XA[i0 + (2 * g) * BLOCK];
        float4 a1 = XA[i0 + (2 * g + 1) * BLOCK];
        float4 b0 = XB[i0 + (2 * g) * BLOCK];
        float4 b1 = XB[i0 + (2 * g + 1) * BLOCK];
        icx[g] = pk(a0.x, a1.x);
        icy[g] = pk(a0.y, a1.y);
        icz[g] = pk(a0.z, a1.z);
        imx[g] = pk(a0.w, a1.w);
        imy[g] = pk(b0.x, b1.x);
        imz[g] = pk(b0.y, b1.y);
    }

    int j0 = blockIdx.y * TJ;
#pragma unroll
    for (int r = 0; r < TJ / BLOCK; r++) {
        sA[threadIdx.x + r * BLOCK] = YA[j0 + threadIdx.x + r * BLOCK];
        sB[threadIdx.x + r * BLOCK] = YB[j0 + threadIdx.x + r * BLOCK];
    }
    __syncthreads();

    ull acc[NG];
#pragma unroll
    for (int g = 0; g < NG; g++) acc[g] = 0ull;   // (0.0f, 0.0f)

#pragma unroll 4
    for (int j = 0; j < TJ; j++) {
        float4 ja = sA[j];
        float4 jb = sB[j];
        ull jx  = pk(ja.x, ja.x);
        ull jy  = pk(ja.y, ja.y);
        ull jz  = pk(ja.z, ja.z);
        ull jmx = pk(ja.w, ja.w);
        ull jmy = pk(jb.x, jb.x);
        ull jmz = pk(jb.y, jb.y);
#pragma unroll
        for (int g = 0; g < NG; g++) {
            ull pc = f2fma(jz, icz[g], f2fma(jy, icy[g], f2mul(jx, icx[g])));
            ull dm = f2fma(jmz, imz[g], f2fma(jmy, imy[g], f2mul(jmx, imx[g])));
            float p0, p1; upk(pc, p0, p1);
            float e0 = ex2(p0);
            float e1 = ex2(p1);
            ull dm2 = f2mul(dm, dm);
            acc[g] = f2fma(dm2, pk(e0, e1), acc[g]);
        }
    }

    float tsum = 0.f;
#pragma unroll
    for (int g = 0; g < NG; g++) {
        float a0, a1; upk(acc[g], a0, a1);
        tsum += a0 + a1;
    }
    red[threadIdx.x] = tsum;
    __syncthreads();
#pragma unroll
    for (int s2 = BLOCK / 2; s2 > 0; s2 >>= 1) {
        if (threadIdx.x < s2) red[threadIdx.x] += red[threadIdx.x + s2];
        __syncthreads();
    }
    if (threadIdx.x == 0) {
        g_part[pidx] = (double)wgt * (double)red[0];
    }
}

__global__ void reduce_kernel(float* __restrict__ out, int n, float invB)
{
    __shared__ double rd[256];
    double s = 0.0;
    for (int i = threadIdx.x; i < n; i += 256) s += g_part[i];
    rd[threadIdx.x] = s;
    __syncthreads();
#pragma unroll
    for (int s2 = 128; s2 > 0; s2 >>= 1) {
        if (threadIdx.x < s2) rd[threadIdx.x] += rd[threadIdx.x + s2];
        __syncthreads();
    }
    if (threadIdx.x == 0) out[0] = (float)(rd[0] * (double)invB);
}

extern "C" void kernel_launch(void* const* d_in, const int* in_sizes, int n_in,
                              void* d_out, int out_size)
{
    const float* pred  = (const float*)d_in[0];
    const float* targ  = (const float*)d_in[1];
    const int*   faces = (const int*)d_in[2];

    int NV = NV_CONST;
    int B  = in_sizes[0] / (NV * 3);
    int NF = in_sizes[2] / 3;
    int NFP = ((NF + TI - 1) / TI) * TI;   // multiple of 2048 (and of TJ=512)
    if (NFP > NFP_MAX) NFP = NFP_MAX;
    if (B > SMAX / 2) B = SMAX / 2;

    int prep_total = 2 * B * NFP;
    prep_kernel<<<(prep_total + 255) / 256, 256>>>(pred, targ, faces, B, NV, NF, NFP);

    int gx = NFP / TI;
    int gy = NFP / TJ;
    dim3 grid(gx, gy, 3 * B);
    pair_kernel<<<grid, BLOCK>>>(B, NFP, gx, gy);

    int nparts = gx * gy * 3 * B;
    reduce_kernel<<<1, 256>>>((float*)d_out, nparts, 1.0f / (float)B);
}

// round 6
// speedup vs baseline: 1.2964x; 1.1382x over previous
#include <cuda_runtime.h>
#include <cuda_bf16.h>

// Varifold loss on GB300 — factored Gaussian, packed-j f32x2 math, fine triangular tiles.
// loss = (1/B) * sum_b [ K(s,s) + K(t,t) - 2 K(s,t) ]
// Factorization:
//   M' = sqrt(L) * Nn * exp(-|c'|^2 / 2)   with c' = C / sigma
//   cs = c' * sqrt(2*log2(e))
//   term_ij = <M'_i, M'_j>^2 * 2^( <cs_i, cs_j> )

#define NV_CONST 5023
#define TI 512           // i-points per block (128 threads x 4)
#define TJ 512           // j-points per smem tile
#define BLOCK 128
#define NI 4             // i-points per thread (each duplicated {v,v})
#define NFP_MAX 10240
#define SMAX 8
#define PART_MAX 8192

__device__ float4 g_A[SMAX * NFP_MAX];   // (cs.x, cs.y, cs.z, M'.x)
__device__ float4 g_Bv[SMAX * NFP_MAX];  // (M'.y, M'.z, 0, 0)
__device__ double g_part[PART_MAX];

typedef unsigned long long ull;

__device__ __forceinline__ ull pk(float a, float b) {
    ull r; asm("mov.b64 %0, {%1,%2};" : "=l"(r) : "f"(a), "f"(b)); return r;
}
__device__ __forceinline__ void upk(ull v, float& a, float& b) {
    asm("mov.b64 {%0,%1}, %2;" : "=f"(a), "=f"(b) : "l"(v));
}
__device__ __forceinline__ ull f2mul(ull a, ull b) {
    ull r; asm("mul.rn.f32x2 %0, %1, %2;" : "=l"(r) : "l"(a), "l"(b)); return r;
}
__device__ __forceinline__ ull f2fma(ull a, ull b, ull c) {
    ull r; asm("fma.rn.f32x2 %0, %1, %2, %3;" : "=l"(r) : "l"(a), "l"(b), "l"(c)); return r;
}
__device__ __forceinline__ float ex2(float x) {
    float r; asm("ex2.approx.f32 %0, %1;" : "=f"(r) : "f"(x)); return r;
}

__global__ void prep_kernel(const float* __restrict__ pred,
                            const float* __restrict__ targ,
                            const int* __restrict__ faces,
                            int B, int NV, int NF, int NFP)
{
    int idx = blockIdx.x * blockDim.x + threadIdx.x;
    int total = 2 * B * NFP;
    if (idx >= total) return;
    int s = idx / NFP;
    int f = idx - s * NFP;

    float4 A = make_float4(0.f, 0.f, 0.f, 0.f);
    float4 Bv = make_float4(0.f, 0.f, 0.f, 0.f);

    if (f < NF) {
        const float* src = (s < B) ? pred : targ;
        int b = (s < B) ? s : (s - B);
        const float* base = src + (size_t)b * NV * 3;

        int i0 = faces[3 * f + 0];
        int i1 = faces[3 * f + 1];
        int i2 = faces[3 * f + 2];

        float x0 = base[3 * i0 + 0], y0 = base[3 * i0 + 1], z0 = base[3 * i0 + 2];
        float x1 = base[3 * i1 + 0], y1 = base[3 * i1 + 1], z1 = base[3 * i1 + 2];
        float x2 = base[3 * i2 + 0], y2 = base[3 * i2 + 1], z2 = base[3 * i2 + 2];

        // c' = centroid / sigma  (sigma = 0.03)
        const float SG = 33.333333333333336f;
        float cx = (x0 + x1 + x2) * (1.0f / 3.0f) * SG;
        float cy = (y0 + y1 + y2) * (1.0f / 3.0f) * SG;
        float cz = (z0 + z1 + z2) * (1.0f / 3.0f) * SG;

        float e1x = x1 - x0, e1y = y1 - y0, e1z = z1 - z0;
        float e2x = x2 - x0, e2y = y2 - y0, e2z = z2 - z0;

        float nx = 0.5f * (e1y * e2z - e1z * e2y);
        float ny = 0.5f * (e1z * e2x - e1x * e2z);
        float nz = 0.5f * (e1x * e2y - e1y * e2x);

        float L = sqrtf(nx * nx + ny * ny + nz * nz);
        // M' = sqrt(L)/max(L,eps) * N * exp(-|c'|^2/2)
        float w = expf(-0.5f * (cx * cx + cy * cy + cz * cz));
        float sc = (sqrtf(L) / fmaxf(L, 1e-12f)) * w;
        float mx = nx * sc, my = ny * sc, mz = nz * sc;

        // cs = c' * sqrt(2*log2(e))  so that dot(cs_i,cs_j) feeds EX2 directly
        const float SQ2LE = 1.6986436006287996f;  // sqrt(2*1.4426950408889634)
        A = make_float4(cx * SQ2LE, cy * SQ2LE, cz * SQ2LE, mx);
        Bv = make_float4(my, mz, 0.f, 0.f);
    }
    g_A[(size_t)s * NFP + f] = A;
    g_Bv[(size_t)s * NFP + f] = Bv;
}

__global__ void __launch_bounds__(BLOCK, 5)
pair_kernel(int B, int NFP, int gx, int gy)
{
    // SoA j-tile: packed pairs of consecutive j-points load as one ld.shared.b64.
    __shared__ float s_x[TJ], s_y[TJ], s_z[TJ];
    __shared__ float s_mx[TJ], s_my[TJ], s_mz[TJ];
    __shared__ float red[BLOCK];

    int z = blockIdx.z;
    int b = z / 3;
    int t = z - 3 * b;           // 0: ss, 1: tt, 2: st
    int pidx = (z * gy + blockIdx.y) * gx + blockIdx.x;

    float wgt = (t == 2) ? -2.f : 1.f;
    if (t < 2) {
        // symmetric kernel, TI == TJ: square tiles, strict triangle
        int jt = blockIdx.y, it = blockIdx.x;
        if (jt < it) {                    // strictly lower: skip
            if (threadIdx.x == 0) g_part[pidx] = 0.0;
            return;
        }
        if (jt > it) wgt = 2.f;           // strictly upper: count twice
    }

    int sx = (t == 1) ? (B + b) : b;
    int sy = (t == 0) ? b : (B + b);

    const float4* __restrict__ XA = g_A  + (size_t)sx * NFP;
    const float4* __restrict__ XB = g_Bv + (size_t)sx * NFP;
    const float4* __restrict__ YA = g_A  + (size_t)sy * NFP;
    const float4* __restrict__ YB = g_Bv + (size_t)sy * NFP;

    // Load NI i-points, duplicate each component {v,v} ONCE (hoisted out of j-loop)
    int i0 = blockIdx.x * TI + threadIdx.x;
    ull icx[NI], icy[NI], icz[NI], imx[NI], imy[NI], imz[NI];
#pragma unroll
    for (int k = 0; k < NI; k++) {
        float4 a = XA[i0 + k * BLOCK];
        float4 v = XB[i0 + k * BLOCK];
        icx[k] = pk(a.x, a.x);
        icy[k] = pk(a.y, a.y);
        icz[k] = pk(a.z, a.z);
        imx[k] = pk(a.w, a.w);
        imy[k] = pk(v.x, v.x);
        imz[k] = pk(v.y, v.y);
    }

    int j0 = blockIdx.y * TJ;
#pragma unroll
    for (int r = 0; r < TJ / BLOCK; r++) {
        int jj = threadIdx.x + r * BLOCK;
        float4 a = YA[j0 + jj];
        float4 v = YB[j0 + jj];
        s_x[jj] = a.x;  s_y[jj] = a.y;  s_z[jj] = a.z;
        s_mx[jj] = a.w; s_my[jj] = v.x; s_mz[jj] = v.y;
    }
    __syncthreads();

    const ull* __restrict__ px  = (const ull*)s_x;
    const ull* __restrict__ py  = (const ull*)s_y;
    const ull* __restrict__ pz  = (const ull*)s_z;
    const ull* __restrict__ pmx = (const ull*)s_mx;
    const ull* __restrict__ pmy = (const ull*)s_my;
    const ull* __restrict__ pmz = (const ull*)s_mz;

    ull acc[NI];
#pragma unroll
    for (int k = 0; k < NI; k++) acc[k] = 0ull;   // (0.0f, 0.0f)

#pragma unroll 4
    for (int j2 = 0; j2 < TJ / 2; j2++) {
        ull jx  = px[j2];
        ull jy  = py[j2];
        ull jz  = pz[j2];
        ull jmx = pmx[j2];
        ull jmy = pmy[j2];
        ull jmz = pmz[j2];
#pragma unroll
        for (int k = 0; k < NI; k++) {
            ull pc = f2fma(jz, icz[k], f2fma(jy, icy[k], f2mul(jx, icx[k])));
            ull dm = f2fma(jmz, imz[k], f2fma(jmy, imy[k], f2mul(jmx, imx[k])));
            float p0, p1; upk(pc, p0, p1);
            float e0 = ex2(p0);
            float e1 = ex2(p1);
            ull dm2 = f2mul(dm, dm);
            acc[k] = f2fma(dm2, pk(e0, e1), acc[k]);
        }
    }

    float tsum = 0.f;
#pragma unroll
    for (int k = 0; k < NI; k++) {
        float a0, a1; upk(acc[k], a0, a1);
        tsum += a0 + a1;
    }
    red[threadIdx.x] = tsum;
    __syncthreads();
#pragma unroll
    for (int s2 = BLOCK / 2; s2 > 0; s2 >>= 1) {
        if (threadIdx.x < s2) red[threadIdx.x] += red[threadIdx.x + s2];
        __syncthreads();
    }
    if (threadIdx.x == 0) {
        g_part[pidx] = (double)wgt * (double)red[0];
    }
}

__global__ void reduce_kernel(float* __restrict__ out, int n, float invB)
{
    __shared__ double rd[256];
    double s = 0.0;
    for (int i = threadIdx.x; i < n; i += 256) s += g_part[i];
    rd[threadIdx.x] = s;
    __syncthreads();
#pragma unroll
    for (int s2 = 128; s2 > 0; s2 >>= 1) {
        if (threadIdx.x < s2) rd[threadIdx.x] += rd[threadIdx.x + s2];
        __syncthreads();
    }
    if (threadIdx.x == 0) out[0] = (float)(rd[0] * (double)invB);
}

extern "C" void kernel_launch(void* const* d_in, const int* in_sizes, int n_in,
                              void* d_out, int out_size)
{
    const float* pred  = (const float*)d_in[0];
    const float* targ  = (const float*)d_in[1];
    const int*   faces = (const int*)d_in[2];

    int NV = NV_CONST;
    int B  = in_sizes[0] / (NV * 3);
    int NF = in_sizes[2] / 3;
    int NFP = ((NF + TI - 1) / TI) * TI;   // multiple of 512
    if (NFP > NFP_MAX) NFP = NFP_MAX;
    if (B > SMAX / 2) B = SMAX / 2;

    int prep_total = 2 * B * NFP;
    prep_kernel<<<(prep_total + 255) / 256, 256>>>(pred, targ, faces, B, NV, NF, NFP);

    int gx = NFP / TI;
    int gy = NFP / TJ;
    dim3 grid(gx, gy, 3 * B);
    pair_kernel<<<grid, BLOCK>>>(B, NFP, gx, gy);

    int nparts = gx * gy * 3 * B;
    reduce_kernel<<<1, 256>>>((float*)d_out, nparts, 1.0f / (float)B);
}